// round 12
// baseline (speedup 1.0000x reference)
#include <cuda_runtime.h>
#include <cstdint>

// Problem constants (fixed by the reference)
constexpr int Bc = 4, S = 2048, D = 2048, H = 16, DH = 128;
constexpr int M_ROWS = Bc * S;  // 8192

// Scratch (device globals: allocation in kernel_launch is forbidden)
__device__ float g_Q[(size_t)M_ROWS * D];
__device__ float g_K[(size_t)M_ROWS * D];
__device__ float g_V[(size_t)M_ROWS * D];
__device__ float g_A[(size_t)M_ROWS * D];
// bf16 split scratch: activations (reused per GEMM) + transposed weights
__device__ unsigned short g_Sh[(size_t)M_ROWS * D];
__device__ unsigned short g_Sl[(size_t)M_ROWS * D];
__device__ unsigned short g_Wth[(size_t)D * D];
__device__ unsigned short g_Wtl[(size_t)D * D];

// ---------------- packed f32x2 helpers (attention FFMA2 path) ---------------
__device__ __forceinline__ unsigned long long dup2(float x) {
    unsigned long long r;
    asm("mov.b64 %0, {%1, %1};" : "=l"(r) : "f"(x));
    return r;
}
__device__ __forceinline__ void fma2(unsigned long long& d, unsigned long long a,
                                     unsigned long long b) {
    asm("fma.rn.f32x2 %0, %1, %2, %0;" : "+l"(d) : "l"(a), "l"(b));
}
__device__ __forceinline__ void mul2(unsigned long long& d, unsigned long long a) {
    asm("mul.rn.f32x2 %0, %0, %1;" : "+l"(d) : "l"(a));
}
__device__ __forceinline__ float2 unpack2(unsigned long long v) {
    float2 f;
    asm("mov.b64 {%0, %1}, %2;" : "=f"(f.x), "=f"(f.y) : "l"(v));
    return f;
}
__device__ __forceinline__ float ex2(float x) {
    float y;
    asm("ex2.approx.ftz.f32 %0, %1;" : "=f"(y) : "f"(x));
    return y;
}

// ---------------- bf16 split helpers ----------------------------------------
__device__ __forceinline__ unsigned short f2bf(float x) {
    unsigned short r;
    asm("cvt.rn.bf16.f32 %0, %1;" : "=h"(r) : "f"(x));
    return r;
}
__device__ __forceinline__ float bf2f(unsigned short h) {
    return __uint_as_float(((unsigned int)h) << 16);
}

// mma.m16n8k16 bf16, fp32 accumulate (compiles on compute_103 — validated R4)
__device__ __forceinline__ void mma16816(float* d, const unsigned* a, const unsigned* b) {
    asm volatile(
        "mma.sync.aligned.m16n8k16.row.col.f32.bf16.bf16.f32 "
        "{%0,%1,%2,%3}, {%4,%5,%6,%7}, {%8,%9}, {%0,%1,%2,%3};"
        : "+f"(d[0]), "+f"(d[1]), "+f"(d[2]), "+f"(d[3])
        : "r"(a[0]), "r"(a[1]), "r"(a[2]), "r"(a[3]), "r"(b[0]), "r"(b[1]));
}

// ---------------- cp.async helpers (sm_80+, legal on compute_103) -----------
__device__ __forceinline__ uint32_t smem_u32(const void* p) {
    uint32_t a;
    asm("{ .reg .u64 t; cvta.to.shared.u64 t, %1; cvt.u32.u64 %0, t; }"
        : "=r"(a) : "l"(p));
    return a;
}
__device__ __forceinline__ void cpa16(uint32_t saddr, const void* g) {
    asm volatile("cp.async.ca.shared.global [%0], [%1], 16;" :: "r"(saddr), "l"(g));
}
__device__ __forceinline__ void cpa_commit() {
    asm volatile("cp.async.commit_group;" ::: "memory");
}
__device__ __forceinline__ void cpa_wait1() {
    asm volatile("cp.async.wait_group 1;" ::: "memory");
}
__device__ __forceinline__ void cpa_wait0() {
    asm volatile("cp.async.wait_group 0;" ::: "memory");
}

// ---------------------------------------------------------------------------
// Split converters (unchanged; cheap)
// ---------------------------------------------------------------------------
__global__ void split_rows(const float4* __restrict__ X, ushort4* __restrict__ Hh,
                           ushort4* __restrict__ Ll, int n4) {
    int i = blockIdx.x * blockDim.x + threadIdx.x;
    if (i >= n4) return;
    float4 v = X[i];
    ushort4 h, l;
    h.x = f2bf(v.x); l.x = f2bf(v.x - bf2f(h.x));
    h.y = f2bf(v.y); l.y = f2bf(v.y - bf2f(h.y));
    h.z = f2bf(v.z); l.z = f2bf(v.z - bf2f(h.z));
    h.w = f2bf(v.w); l.w = f2bf(v.w - bf2f(h.w));
    Hh[i] = h;
    Ll[i] = l;
}

// Wt[n][k] = W[k][n], split hi/lo.  Block (32,8), tile 32x32 via smem.
__global__ void split_T(const float* __restrict__ W, unsigned short* __restrict__ Ht,
                        unsigned short* __restrict__ Lt, int Kd, int Nd) {
    __shared__ float t[32][33];
    const int n0 = blockIdx.x * 32, k0 = blockIdx.y * 32;
    const int tx = threadIdx.x, ty = threadIdx.y;
#pragma unroll
    for (int r = ty; r < 32; r += 8) t[r][tx] = W[(size_t)(k0 + r) * Nd + n0 + tx];
    __syncthreads();
#pragma unroll
    for (int r = ty; r < 32; r += 8) {
        float v = t[tx][r];  // = W[k0+tx][n0+r]
        size_t o = (size_t)(n0 + r) * Kd + k0 + tx;
        unsigned short h = f2bf(v);
        Ht[o] = h;
        Lt[o] = f2bf(v - bf2f(h));
    }
}

// ---------------------------------------------------------------------------
// HMMA GEMM, double-buffered cp.async, pre-split bf16 inputs.
//   C[M,N] = A@W + bias via 3-pass split: Ah@Bh + Ah@Bl + Al@Bh
// A-side: Ah/Al [M,K] K-major bf16.  B-side: Bh/Bl = W^T [N,K] K-major bf16.
// CTA 128x128, BK=32, 256 threads (8 warps: 4(M) x 2(N), warp tile 32x64).
// smem pitch 40 halves (80B rows): conflict-free frag loads, 16B cp.async ok.
// ---------------------------------------------------------------------------
constexpr int GP = 40;                       // smem pitch in halves
constexpr int TILE_H = 128 * GP;             // one tile (halves)
constexpr int STAGE_H = 4 * TILE_H;          // AH,AL,BH,BL (halves)
constexpr int GEMM_SMEM2 = 2 * STAGE_H * 2;  // 2 stages, bytes = 81920

__global__ __launch_bounds__(256)
void gemm_hmma(const unsigned short* __restrict__ Ah_g, const unsigned short* __restrict__ Al_g,
               const unsigned short* __restrict__ Bh_g, const unsigned short* __restrict__ Bl_g,
               const float* __restrict__ bias, float* __restrict__ C,
               int M, int N, int K) {
    extern __shared__ unsigned short smh[];
    const uint32_t sb = smem_u32(smh);

    const int tid = threadIdx.x;
    const int wid = tid >> 5, lane = tid & 31;
    const int g = lane >> 2, t = lane & 3;
    const int wm = (wid & 3) * 32;   // warp M offset
    const int wn = (wid >> 2) * 64;  // warp N offset
    const int m0 = blockIdx.y * 128, n0 = blockIdx.x * 128;

    float acc[2][8][4];
#pragma unroll
    for (int mi = 0; mi < 2; mi++)
#pragma unroll
        for (int ni = 0; ni < 8; ni++)
#pragma unroll
            for (int r = 0; r < 4; r++) acc[mi][ni][r] = 0.f;

    // ---- stage loader: 8x 16B cp.async per thread -------------------------
    // chunk c (0..511): row = c>>2 (0..127), cc = c&3 (16B chunk in 64B row)
    auto load_stage = [&](int kc, int buf) {
        const int kb0 = kc * 32;  // k offset (halves)
#pragma unroll
        for (int j = 0; j < 2; j++) {
            const int c = tid + 256 * j;
            const int row = c >> 2, cc = c & 3;
            const int kh = kb0 + cc * 8;
            const uint32_t so = sb + 2u * (buf * STAGE_H + row * GP + cc * 8);
            const size_t ga = (size_t)(m0 + row) * K + kh;
            const size_t gb = (size_t)(n0 + row) * K + kh;
            cpa16(so + 0 * 2 * TILE_H, Ah_g + ga);
            cpa16(so + 1 * 2 * TILE_H, Al_g + ga);
            cpa16(so + 2 * 2 * TILE_H, Bh_g + gb);
            cpa16(so + 3 * 2 * TILE_H, Bl_g + gb);
        }
        cpa_commit();
    };

    const int NC = K / 32;  // 64 stages
    load_stage(0, 0);

    for (int kc = 0; kc < NC; kc++) {
        const int buf = kc & 1;
        if (kc + 1 < NC) {
            load_stage(kc + 1, 1 - buf);
            cpa_wait1();
        } else {
            cpa_wait0();
        }
        __syncthreads();

        const unsigned short* SA_h = smh + buf * STAGE_H + 0 * TILE_H;
        const unsigned short* SA_l = smh + buf * STAGE_H + 1 * TILE_H;
        const unsigned short* SB_h = smh + buf * STAGE_H + 2 * TILE_H;
        const unsigned short* SB_l = smh + buf * STAGE_H + 3 * TILE_H;

#pragma unroll
        for (int ks = 0; ks < 2; ks++) {
            const int kb = ks * 16;
            unsigned ah[2][4], al[2][4], bh[8][2], bl[8][2];
#pragma unroll
            for (int mi = 0; mi < 2; mi++) {
                const int r0 = (wm + mi * 16 + g) * GP;
                const int r8 = (wm + mi * 16 + 8 + g) * GP;
                ah[mi][0] = *(const unsigned*)&SA_h[r0 + kb + 2 * t];
                ah[mi][1] = *(const unsigned*)&SA_h[r8 + kb + 2 * t];
                ah[mi][2] = *(const unsigned*)&SA_h[r0 + kb + 8 + 2 * t];
                ah[mi][3] = *(const unsigned*)&SA_h[r8 + kb + 8 + 2 * t];
                al[mi][0] = *(const unsigned*)&SA_l[r0 + kb + 2 * t];
                al[mi][1] = *(const unsigned*)&SA_l[r8 + kb + 2 * t];
                al[mi][2] = *(const unsigned*)&SA_l[r0 + kb + 8 + 2 * t];
                al[mi][3] = *(const unsigned*)&SA_l[r8 + kb + 8 + 2 * t];
            }
#pragma unroll
            for (int ni = 0; ni < 8; ni++) {
                const int rn = (wn + ni * 8 + g) * GP;
                bh[ni][0] = *(const unsigned*)&SB_h[rn + kb + 2 * t];
                bh[ni][1] = *(const unsigned*)&SB_h[rn + kb + 8 + 2 * t];
                bl[ni][0] = *(const unsigned*)&SB_l[rn + kb + 2 * t];
                bl[ni][1] = *(const unsigned*)&SB_l[rn + kb + 8 + 2 * t];
            }
#pragma unroll
            for (int mi = 0; mi < 2; mi++)
#pragma unroll
                for (int ni = 0; ni < 8; ni++) mma16816(acc[mi][ni], ah[mi], bh[ni]);
#pragma unroll
            for (int mi = 0; mi < 2; mi++)
#pragma unroll
                for (int ni = 0; ni < 8; ni++) mma16816(acc[mi][ni], ah[mi], bl[ni]);
#pragma unroll
            for (int mi = 0; mi < 2; mi++)
#pragma unroll
                for (int ni = 0; ni < 8; ni++) mma16816(acc[mi][ni], al[mi], bh[ni]);
        }
        __syncthreads();  // before the buffer is refilled
    }

    // ---- epilogue: bias + store -------------------------------------------
#pragma unroll
    for (int mi = 0; mi < 2; mi++) {
        const int row = m0 + wm + mi * 16 + g;
#pragma unroll
        for (int ni = 0; ni < 8; ni++) {
            const int col = n0 + wn + ni * 8 + 2 * t;
            const float b0 = bias[col], b1 = bias[col + 1];
            *(float2*)(C + (size_t)row * N + col) =
                make_float2(acc[mi][ni][0] + b0, acc[mi][ni][1] + b1);
            *(float2*)(C + (size_t)(row + 8) * N + col) =
                make_float2(acc[mi][ni][2] + b0, acc[mi][ni][3] + b1);
        }
    }
}

// ---------------------------------------------------------------------------
// Fused attention faithful to the reference (unchanged; passing since R3):
//   p = softmax over ALL keys (full-row denominator)
//   out[q] = sum_{k<=q} p[q,k] V[k]  - 1e9 * sum_{k>q} V[k]
// ---------------------------------------------------------------------------
constexpr float SCALE_LOG2E = 0.08838834764831845f * 1.4426950408889634f;
constexpr int TP = 132;
constexpr size_t ATTN_SMEM = (size_t)(3 * 128 * TP + 256) * sizeof(float);

__global__ __launch_bounds__(256, 1)
void attn_kernel(const float* __restrict__ Q, const float* __restrict__ K,
                 const float* __restrict__ V, float* __restrict__ O) {
    extern __shared__ float sm[];
    float* Qs = sm;
    float* B1 = sm + 128 * TP;
    float* Vs = sm + 2 * 128 * TP;
    float* scr = sm + 3 * 128 * TP;

    const int tid = threadIdx.x;
    const int tx = tid & 15;
    const int ty = tid >> 4;
    const int qb = blockIdx.x;
    const int h = blockIdx.y;
    const int b = blockIdx.z;
    const int q0 = qb * 128;

    const float* Qg = Q + ((size_t)b * S + q0) * D + h * DH;
    const float* Kg = K + (size_t)b * S * D + h * DH;
    const float* Vg = V + (size_t)b * S * D + h * DH;

    {
        const int lane = tid & 31;
#pragma unroll
        for (int it = 0; it < 16; it++) {
            int row = it * 8 + (tid >> 5);
            float4 v = *(const float4*)(Qg + (size_t)row * D + lane * 4);
            v.x *= SCALE_LOG2E; v.y *= SCALE_LOG2E;
            v.z *= SCALE_LOG2E; v.w *= SCALE_LOG2E;
            *(float4*)&Qs[row * TP + lane * 4] = v;
        }
    }

    unsigned long long acc[8][4];
#pragma unroll
    for (int i = 0; i < 8; i++)
#pragma unroll
        for (int j = 0; j < 4; j++) acc[i][j] = 0ull;
    float m_r[8], l_r[8];
#pragma unroll
    for (int i = 0; i < 8; i++) { m_r[i] = -1e30f; l_r[i] = 0.f; }

    float psum = 0.f;
    const int cd = tid & 127;
    const int ck0 = (tid >> 7) * 64;

    constexpr int NT = S / 128;
    for (int tix = 0; tix < NT; tix++) {
        const int j = (tix < NT - 1) ? (tix < qb ? tix : tix + 1) : qb;

        {
            const int r2 = tid >> 1, c2 = (tid & 1) * 64;
            const float* Kr = Kg + (size_t)(j * 128 + r2) * D + c2;
            const float* Vr = Vg + (size_t)(j * 128 + r2) * D + c2;
#pragma unroll
            for (int f = 0; f < 16; f++) {
                float4 kv = *(const float4*)(Kr + f * 4);
                B1[(c2 + f * 4 + 0) * TP + r2] = kv.x;
                B1[(c2 + f * 4 + 1) * TP + r2] = kv.y;
                B1[(c2 + f * 4 + 2) * TP + r2] = kv.z;
                B1[(c2 + f * 4 + 3) * TP + r2] = kv.w;
                *(float4*)&Vs[r2 * TP + c2 + f * 4] = *(const float4*)(Vr + f * 4);
            }
        }
        __syncthreads();

        unsigned long long sacc[8][4];
#pragma unroll
        for (int i = 0; i < 8; i++)
#pragma unroll
            for (int jp = 0; jp < 4; jp++) sacc[i][jp] = 0ull;

        for (int d0 = 0; d0 < 128; d0 += 2) {
            float2 qv[8];
#pragma unroll
            for (int i = 0; i < 8; i++)
                qv[i] = *(const float2*)&Qs[(ty * 8 + i) * TP + d0];
#pragma unroll
            for (int dd = 0; dd < 2; dd++) {
                ulonglong2 b0 = *(const ulonglong2*)&B1[(d0 + dd) * TP + tx * 4];
                ulonglong2 b1 = *(const ulonglong2*)&B1[(d0 + dd) * TP + 64 + tx * 4];
#pragma unroll
                for (int i = 0; i < 8; i++) {
                    unsigned long long ad = dup2(dd ? qv[i].y : qv[i].x);
                    fma2(sacc[i][0], ad, b0.x);
                    fma2(sacc[i][1], ad, b0.y);
                    fma2(sacc[i][2], ad, b1.x);
                    fma2(sacc[i][3], ad, b1.y);
                }
            }
        }

        float p[8][8];
#pragma unroll
        for (int i = 0; i < 8; i++) {
#pragma unroll
            for (int jp = 0; jp < 4; jp++) {
                float2 f = unpack2(sacc[i][jp]);
                p[i][2 * jp] = f.x;
                p[i][2 * jp + 1] = f.y;
            }
            float rm = p[i][0];
#pragma unroll
            for (int jj = 1; jj < 8; jj++) rm = fmaxf(rm, p[i][jj]);
            rm = fmaxf(rm, __shfl_xor_sync(0xffffffffu, rm, 1));
            rm = fmaxf(rm, __shfl_xor_sync(0xffffffffu, rm, 2));
            rm = fmaxf(rm, __shfl_xor_sync(0xffffffffu, rm, 4));
            rm = fmaxf(rm, __shfl_xor_sync(0xffffffffu, rm, 8));
            float mn = fmaxf(m_r[i], rm);
            float fac = ex2(m_r[i] - mn);
            m_r[i] = mn;
            float rs = 0.f;
#pragma unroll
            for (int jj = 0; jj < 8; jj++) {
                float e = ex2(p[i][jj] - mn);
                p[i][jj] = e;
                rs += e;
            }
            rs += __shfl_xor_sync(0xffffffffu, rs, 1);
            rs += __shfl_xor_sync(0xffffffffu, rs, 2);
            rs += __shfl_xor_sync(0xffffffffu, rs, 4);
            rs += __shfl_xor_sync(0xffffffffu, rs, 8);
            l_r[i] = l_r[i] * fac + rs;
            unsigned long long fd = dup2(fac);
#pragma unroll
            for (int jp = 0; jp < 4; jp++) mul2(acc[i][jp], fd);
        }

        if (j <= qb) {
            if (j == qb) {
#pragma unroll
                for (int i = 0; i < 8; i++)
#pragma unroll
                    for (int jj = 0; jj < 8; jj++) {
                        int col = (jj < 4) ? tx * 4 + jj : 64 + tx * 4 + jj - 4;
                        if (col > ty * 8 + i) p[i][jj] = 0.f;
                    }
            }
            __syncthreads();
#pragma unroll
            for (int i = 0; i < 8; i++) {
                *(float4*)&B1[(ty * 8 + i) * TP + tx * 4] =
                    make_float4(p[i][0], p[i][1], p[i][2], p[i][3]);
                *(float4*)&B1[(ty * 8 + i) * TP + 64 + tx * 4] =
                    make_float4(p[i][4], p[i][5], p[i][6], p[i][7]);
            }
            __syncthreads();
            for (int k0 = 0; k0 < 128; k0 += 2) {
                float2 pv[8];
#pragma unroll
                for (int i = 0; i < 8; i++)
                    pv[i] = *(const float2*)&B1[(ty * 8 + i) * TP + k0];
#pragma unroll
                for (int kk = 0; kk < 2; kk++) {
                    ulonglong2 b0 = *(const ulonglong2*)&Vs[(k0 + kk) * TP + tx * 4];
                    ulonglong2 b1 = *(const ulonglong2*)&Vs[(k0 + kk) * TP + 64 + tx * 4];
#pragma unroll
                    for (int i = 0; i < 8; i++) {
                        unsigned long long ad = dup2(kk ? pv[i].y : pv[i].x);
                        fma2(acc[i][0], ad, b0.x);
                        fma2(acc[i][1], ad, b0.y);
                        fma2(acc[i][2], ad, b1.x);
                        fma2(acc[i][3], ad, b1.y);
                    }
                }
            }
        } else {
            for (int k = ck0; k < ck0 + 64; k++) psum += Vs[k * TP + cd];
        }
        __syncthreads();
    }

    scr[tid] = psum;
    __syncthreads();
    if (tid < 128) scr[tid] += scr[tid + 128];
    __syncthreads();

    float inv_l[8];
#pragma unroll
    for (int i = 0; i < 8; i++) inv_l[i] = 1.f / l_r[i];
    float sfv[8];
#pragma unroll
    for (int jj = 0; jj < 8; jj++) {
        int col = (jj < 4) ? tx * 4 + jj : 64 + tx * 4 + jj - 4;
        sfv[jj] = scr[col];
    }

    const int qlo = ty * 8;
    float run[8];
#pragma unroll
    for (int jj = 0; jj < 8; jj++) run[jj] = 0.f;

    float* Obase = O + ((size_t)b * S + q0) * D + h * DH;
    int kk = 127;
#pragma unroll
    for (int i = 7; i >= 0; --i) {
        const int q = qlo + i;
        for (; kk > q; --kk) {
            float4 v0 = *(const float4*)&Vs[kk * TP + tx * 4];
            float4 v1 = *(const float4*)&Vs[kk * TP + 64 + tx * 4];
            run[0] += v0.x; run[1] += v0.y; run[2] += v0.z; run[3] += v0.w;
            run[4] += v1.x; run[5] += v1.y; run[6] += v1.z; run[7] += v1.w;
        }
        float o[8];
#pragma unroll
        for (int jp = 0; jp < 4; jp++) {
            float2 f = unpack2(acc[i][jp]);
            o[2 * jp] = f.x;
            o[2 * jp + 1] = f.y;
        }
#pragma unroll
        for (int jj = 0; jj < 8; jj++)
            o[jj] = o[jj] * inv_l[i] - 1e9f * (sfv[jj] + run[jj]);
        float* Op = Obase + (size_t)q * D;
        *(float4*)(Op + tx * 4) = make_float4(o[0], o[1], o[2], o[3]);
        *(float4*)(Op + 64 + tx * 4) = make_float4(o[4], o[5], o[6], o[7]);
    }
}

// ---------------------------------------------------------------------------
extern "C" void kernel_launch(void* const* d_in, const int* in_sizes, int n_in,
                              void* d_out, int out_size) {
    const float* q  = (const float*)d_in[0];
    const float* k  = (const float*)d_in[1];
    const float* v  = (const float*)d_in[2];
    const float* Wq = (const float*)d_in[3];
    const float* bq = (const float*)d_in[4];
    const float* Wk = (const float*)d_in[5];
    const float* bk = (const float*)d_in[6];
    const float* Wv = (const float*)d_in[7];
    const float* bv = (const float*)d_in[8];
    const float* Wo = (const float*)d_in[9];
    const float* bo = (const float*)d_in[10];
    float* out = (float*)d_out;

    float *Qb, *Kb, *Vb, *Ab;
    unsigned short *Sh, *Sl, *Wth, *Wtl;
    cudaGetSymbolAddress((void**)&Qb, g_Q);
    cudaGetSymbolAddress((void**)&Kb, g_K);
    cudaGetSymbolAddress((void**)&Vb, g_V);
    cudaGetSymbolAddress((void**)&Ab, g_A);
    cudaGetSymbolAddress((void**)&Sh, g_Sh);
    cudaGetSymbolAddress((void**)&Sl, g_Sl);
    cudaGetSymbolAddress((void**)&Wth, g_Wth);
    cudaGetSymbolAddress((void**)&Wtl, g_Wtl);

    cudaFuncSetAttribute(attn_kernel, cudaFuncAttributeMaxDynamicSharedMemorySize,
                         (int)ATTN_SMEM);
    cudaFuncSetAttribute(gemm_hmma, cudaFuncAttributeMaxDynamicSharedMemorySize,
                         GEMM_SMEM2);

    const int n4 = (M_ROWS * D) / 4;
    const dim3 cgrid(n4 / 256), cblk(256);
    const dim3 tgrid(D / 32, D / 32), tblk(32, 8);
    const dim3 ggrid(D / 128, M_ROWS / 128);  // (16, 64)

    // Q projection
    split_rows<<<cgrid, cblk>>>((const float4*)q, (ushort4*)Sh, (ushort4*)Sl, n4);
    split_T<<<tgrid, tblk>>>(Wq, Wth, Wtl, D, D);
    gemm_hmma<<<ggrid, 256, GEMM_SMEM2>>>(Sh, Sl, Wth, Wtl, bq, Qb, M_ROWS, D, D);
    // K projection
    split_rows<<<cgrid, cblk>>>((const float4*)k, (ushort4*)Sh, (ushort4*)Sl, n4);
    split_T<<<tgrid, tblk>>>(Wk, Wth, Wtl, D, D);
    gemm_hmma<<<ggrid, 256, GEMM_SMEM2>>>(Sh, Sl, Wth, Wtl, bk, Kb, M_ROWS, D, D);
    // V projection
    split_rows<<<cgrid, cblk>>>((const float4*)v, (ushort4*)Sh, (ushort4*)Sl, n4);
    split_T<<<tgrid, tblk>>>(Wv, Wth, Wtl, D, D);
    gemm_hmma<<<ggrid, 256, GEMM_SMEM2>>>(Sh, Sl, Wth, Wtl, bv, Vb, M_ROWS, D, D);

    attn_kernel<<<dim3(S / 128, H, Bc), 256, ATTN_SMEM>>>(Qb, Kb, Vb, Ab);

    // Output projection
    split_rows<<<cgrid, cblk>>>((const float4*)Ab, (ushort4*)Sh, (ushort4*)Sl, n4);
    split_T<<<tgrid, tblk>>>(Wo, Wth, Wtl, D, D);
    gemm_hmma<<<ggrid, 256, GEMM_SMEM2>>>(Sh, Sl, Wth, Wtl, bo, out, M_ROWS, D, D);
}